// round 1
// baseline (speedup 1.0000x reference)
#include <cuda_runtime.h>
#include <cuda_bf16.h>

#define Nn    8192
#define FIN   512
#define FOUT  256
#define LALPHA 0.2f
#define NSPLIT 2

// ---------------- scratch (device globals: allowed) ----------------
__device__ float d_Wh[(size_t)Nn * FOUT];          // 8 MB
__device__ float d_f1[Nn];
__device__ float d_f2[Nn];
__device__ int   d_gmaxkey;
__device__ float d_accpart[(size_t)NSPLIT * Nn * FOUT];  // 16 MB
__device__ float d_spart[(size_t)NSPLIT * Nn];

__global__ void init_kernel() { d_gmaxkey = (int)0x80000000; }

// ---------------- Wh = h @ W  (8192x512 @ 512x256) ----------------
// 64x64 tile, BK=16, 256 threads, 4x4 per thread.
__global__ void gemm_wh(const float* __restrict__ h, const float* __restrict__ W) {
    __shared__ float As[16][64];   // transposed: As[k][m]
    __shared__ float Bs[16][64];
    int t  = threadIdx.x;
    int bm = blockIdx.x * 64;
    int bn = blockIdx.y * 64;
    int r0 = (t >> 4) * 4;
    int c0 = (t & 15) * 4;
    int arow = t >> 2, akq = (t & 3) * 4;
    int bkk  = t >> 4, bn4 = (t & 15) * 4;

    float acc[4][4];
#pragma unroll
    for (int i = 0; i < 4; i++)
#pragma unroll
        for (int j = 0; j < 4; j++) acc[i][j] = 0.f;

    for (int k0 = 0; k0 < FIN; k0 += 16) {
        float4 av = *(const float4*)&h[(size_t)(bm + arow) * FIN + k0 + akq];
        As[akq + 0][arow] = av.x;
        As[akq + 1][arow] = av.y;
        As[akq + 2][arow] = av.z;
        As[akq + 3][arow] = av.w;
        *(float4*)&Bs[bkk][bn4] =
            *(const float4*)&W[(size_t)(k0 + bkk) * FOUT + bn + bn4];
        __syncthreads();
#pragma unroll
        for (int kk = 0; kk < 16; kk++) {
            float4 a4 = *(float4*)&As[kk][r0];
            float4 b4 = *(float4*)&Bs[kk][c0];
            acc[0][0] += a4.x * b4.x; acc[0][1] += a4.x * b4.y;
            acc[0][2] += a4.x * b4.z; acc[0][3] += a4.x * b4.w;
            acc[1][0] += a4.y * b4.x; acc[1][1] += a4.y * b4.y;
            acc[1][2] += a4.y * b4.z; acc[1][3] += a4.y * b4.w;
            acc[2][0] += a4.z * b4.x; acc[2][1] += a4.z * b4.y;
            acc[2][2] += a4.z * b4.z; acc[2][3] += a4.z * b4.w;
            acc[3][0] += a4.w * b4.x; acc[3][1] += a4.w * b4.y;
            acc[3][2] += a4.w * b4.z; acc[3][3] += a4.w * b4.w;
        }
        __syncthreads();
    }
#pragma unroll
    for (int i = 0; i < 4; i++) {
        float4 v = make_float4(acc[i][0], acc[i][1], acc[i][2], acc[i][3]);
        *(float4*)&d_Wh[(size_t)(bm + r0 + i) * FOUT + bn + c0] = v;
    }
}

// ---------------- f1, f2 and global max(f2) ----------------
// one warp per row
__global__ void f12_kernel(const float* __restrict__ a) {
    int lane = threadIdx.x & 31, warp = threadIdx.x >> 5;
    int row  = blockIdx.x * 8 + warp;
    const float* wr = &d_Wh[(size_t)row * FOUT];
    float s1 = 0.f, s2 = 0.f;
#pragma unroll
    for (int q = 0; q < 2; q++) {
        int c = q * 128 + lane * 4;
        float4 v  = *(const float4*)&wr[c];
        float4 a1 = *(const float4*)&a[c];
        float4 a2 = *(const float4*)&a[FOUT + c];
        s1 += v.x * a1.x + v.y * a1.y + v.z * a1.z + v.w * a1.w;
        s2 += v.x * a2.x + v.y * a2.y + v.z * a2.z + v.w * a2.w;
    }
#pragma unroll
    for (int o = 16; o; o >>= 1) {
        s1 += __shfl_xor_sync(0xffffffffu, s1, o);
        s2 += __shfl_xor_sync(0xffffffffu, s2, o);
    }
    if (lane == 0) {
        d_f1[row] = s1;
        d_f2[row] = s2;
        int b   = __float_as_int(s2);
        int key = b >= 0 ? b : (b ^ 0x7fffffff);  // order-preserving float->int
        atomicMax(&d_gmaxkey, key);
    }
}

// ---------------- fused masked-softmax attention @ Wh ----------------
// Block: 64 rows x 256 cols; j split across blockIdx.y into NSPLIT halves.
// Per 32-j chunk: stage Wh tile in smem, compute P tile (exp(LReLU(f1+f2)-m)
// masked by adj), warp-reduce row sums, then fp32 FFMA microkernel.
__global__ void __launch_bounds__(256, 2) attn_kernel(const int* __restrict__ adj) {
    __shared__ float WhS[32][256];   // 32 KB
    __shared__ float Ps[64][32];     // 8 KB
    __shared__ float f1s[64];
    __shared__ float ms[64];

    int t    = threadIdx.x;
    int lane = t & 31, warp = t >> 5;
    int i0   = blockIdx.x * 64;
    int split = blockIdx.y;

    int kk = d_gmaxkey;
    float gm = __int_as_float(kk >= 0 ? kk : (kk ^ 0x7fffffff));

    if (t < 64) {
        float f = d_f1[i0 + t];
        f1s[t] = f;
        float m = f + gm;
        ms[t] = m > 0.f ? m : LALPHA * m;   // LReLU(f1_i + max f2) >= row max of e
    }
    __syncthreads();

    float4 acc[16];
#pragma unroll
    for (int r = 0; r < 16; r++) acc[r] = make_float4(0.f, 0.f, 0.f, 0.f);
    float ssum[8];
#pragma unroll
    for (int q = 0; q < 8; q++) ssum[q] = 0.f;

    int c0 = (t & 63) * 4;        // 4 consecutive output cols
    int r0 = (t >> 6) * 16;       // 16 rows

    int jbeg = split * (Nn / NSPLIT);
    int jend = jbeg + (Nn / NSPLIT);

    for (int j0 = jbeg; j0 < jend; j0 += 32) {
        // stage Wh[j0:j0+32, 0:256]
#pragma unroll
        for (int q = 0; q < 8; q++) {
            int flat = q * 256 + t;
            int jj = flat >> 6, c4 = (flat & 63) * 4;
            *(float4*)&WhS[jj][c4] =
                *(const float4*)&d_Wh[(size_t)(j0 + jj) * FOUT + c4];
        }
        // P tile: warp w handles rows {q*8+w}, lane = jj
        float f2j = d_f2[j0 + lane];
#pragma unroll
        for (int q = 0; q < 8; q++) {
            int r  = q * 8 + warp;
            int ad = adj[(size_t)(i0 + r) * Nn + j0 + lane];
            float e = f1s[r] + f2j;
            e = e > 0.f ? e : LALPHA * e;
            float p = (ad > 0) ? __expf(e - ms[r]) : 0.f;
            Ps[r][lane] = p;
            float s = p;
#pragma unroll
            for (int o = 16; o; o >>= 1) s += __shfl_xor_sync(0xffffffffu, s, o);
            ssum[q] += s;
        }
        __syncthreads();

        // microkernel: acc[16][4] += P[r][jj] * Wh[jj][c]
#pragma unroll 4
        for (int jj = 0; jj < 32; jj++) {
            float4 wv = *(float4*)&WhS[jj][c0];
#pragma unroll
            for (int r = 0; r < 16; r++) {
                float p = Ps[r0 + r][jj];
                acc[r].x += p * wv.x;
                acc[r].y += p * wv.y;
                acc[r].z += p * wv.z;
                acc[r].w += p * wv.w;
            }
        }
        __syncthreads();
    }

    float* ap = &d_accpart[((size_t)split * Nn + i0) * FOUT];
#pragma unroll
    for (int r = 0; r < 16; r++)
        *(float4*)&ap[(size_t)(r0 + r) * FOUT + c0] = acc[r];
    if (lane == 0) {
#pragma unroll
        for (int q = 0; q < 8; q++)
            d_spart[(size_t)split * Nn + i0 + q * 8 + warp] = ssum[q];
    }
}

// ---------------- combine splits, normalize, ELU ----------------
__global__ void combine_kernel(float* __restrict__ out) {
    int i = blockIdx.x, c = threadIdx.x;
    float s = d_spart[i] + d_spart[Nn + i];
    float v = d_accpart[(size_t)i * FOUT + c] +
              d_accpart[(size_t)Nn * FOUT + (size_t)i * FOUT + c];
    float x = v / s;
    out[(size_t)i * FOUT + c] = x > 0.f ? x : expm1f(x);
}

extern "C" void kernel_launch(void* const* d_in, const int* in_sizes, int n_in,
                              void* d_out, int out_size) {
    const float* h   = (const float*)d_in[0];
    const int*   adj = (const int*)d_in[1];
    const float* W   = (const float*)d_in[2];
    const float* a   = (const float*)d_in[3];
    float* out = (float*)d_out;

    init_kernel<<<1, 1>>>();
    dim3 g1(Nn / 64, FOUT / 64);
    gemm_wh<<<g1, 256>>>(h, W);
    f12_kernel<<<Nn / 8, 256>>>(a);
    dim3 g3(Nn / 64, NSPLIT);
    attn_kernel<<<g3, 256>>>(adj);
    combine_kernel<<<Nn, 256>>>(out);
}

// round 2
// speedup vs baseline: 1.2543x; 1.2543x over previous
#include <cuda_runtime.h>
#include <cuda_bf16.h>

#define Nn    8192
#define FIN   512
#define FOUT  256
#define LALPHA 0.2f
#define NSPLIT 2

typedef unsigned long long ull;

// ---------------- scratch (device globals: allowed) ----------------
__device__ float d_Wh[(size_t)Nn * FOUT];          // 8 MB
__device__ float d_f1[Nn];
__device__ float d_f2[Nn];
__device__ float d_A[Nn];   // exp(f1+gm-m)
__device__ float d_C[Nn];   // exp(0.2(f1+gm)-m)
__device__ float d_B[Nn];   // exp(f2-gm)
__device__ float d_D[Nn];   // exp(0.2(f2-gm))
__device__ int   d_gmaxkey;
__device__ float d_accpart[(size_t)NSPLIT * Nn * FOUT];  // 16 MB
__device__ float d_spart[(size_t)NSPLIT * Nn];

__global__ void init_kernel() { d_gmaxkey = (int)0x80000000; }

__device__ __forceinline__ ull dup2(float x) {
    ull r; asm("mov.b64 %0, {%1, %1};" : "=l"(r) : "f"(x)); return r;
}
__device__ __forceinline__ void ffma2(ull& d, ull a, ull b) {
    asm("fma.rn.f32x2 %0, %1, %2, %0;" : "+l"(d) : "l"(a), "l"(b));
}
__device__ __forceinline__ void unpk(float& lo, float& hi, ull v) {
    asm("mov.b64 {%0, %1}, %2;" : "=f"(lo), "=f"(hi) : "l"(v));
}

// ---------------- Wh = h @ W  (8192x512 @ 512x256) ----------------
__global__ void gemm_wh(const float* __restrict__ h, const float* __restrict__ W) {
    __shared__ float As[16][64];
    __shared__ float Bs[16][64];
    int t  = threadIdx.x;
    int bm = blockIdx.x * 64;
    int bn = blockIdx.y * 64;
    int r0 = (t >> 4) * 4;
    int c0 = (t & 15) * 4;
    int arow = t >> 2, akq = (t & 3) * 4;
    int bkk  = t >> 4, bn4 = (t & 15) * 4;

    float acc[4][4];
#pragma unroll
    for (int i = 0; i < 4; i++)
#pragma unroll
        for (int j = 0; j < 4; j++) acc[i][j] = 0.f;

    for (int k0 = 0; k0 < FIN; k0 += 16) {
        float4 av = *(const float4*)&h[(size_t)(bm + arow) * FIN + k0 + akq];
        As[akq + 0][arow] = av.x;
        As[akq + 1][arow] = av.y;
        As[akq + 2][arow] = av.z;
        As[akq + 3][arow] = av.w;
        *(float4*)&Bs[bkk][bn4] =
            *(const float4*)&W[(size_t)(k0 + bkk) * FOUT + bn + bn4];
        __syncthreads();
#pragma unroll
        for (int kk = 0; kk < 16; kk++) {
            float4 a4 = *(float4*)&As[kk][r0];
            float4 b4 = *(float4*)&Bs[kk][c0];
            acc[0][0] += a4.x * b4.x; acc[0][1] += a4.x * b4.y;
            acc[0][2] += a4.x * b4.z; acc[0][3] += a4.x * b4.w;
            acc[1][0] += a4.y * b4.x; acc[1][1] += a4.y * b4.y;
            acc[1][2] += a4.y * b4.z; acc[1][3] += a4.y * b4.w;
            acc[2][0] += a4.z * b4.x; acc[2][1] += a4.z * b4.y;
            acc[2][2] += a4.z * b4.z; acc[2][3] += a4.z * b4.w;
            acc[3][0] += a4.w * b4.x; acc[3][1] += a4.w * b4.y;
            acc[3][2] += a4.w * b4.z; acc[3][3] += a4.w * b4.w;
        }
        __syncthreads();
    }
#pragma unroll
    for (int i = 0; i < 4; i++) {
        float4 v = make_float4(acc[i][0], acc[i][1], acc[i][2], acc[i][3]);
        *(float4*)&d_Wh[(size_t)(bm + r0 + i) * FOUT + bn + c0] = v;
    }
}

// ---------------- f1, f2 and global max(f2) ----------------
__global__ void f12_kernel(const float* __restrict__ a) {
    int lane = threadIdx.x & 31, warp = threadIdx.x >> 5;
    int row  = blockIdx.x * 8 + warp;
    const float* wr = &d_Wh[(size_t)row * FOUT];
    float s1 = 0.f, s2 = 0.f;
#pragma unroll
    for (int q = 0; q < 2; q++) {
        int c = q * 128 + lane * 4;
        float4 v  = *(const float4*)&wr[c];
        float4 a1 = *(const float4*)&a[c];
        float4 a2 = *(const float4*)&a[FOUT + c];
        s1 += v.x * a1.x + v.y * a1.y + v.z * a1.z + v.w * a1.w;
        s2 += v.x * a2.x + v.y * a2.y + v.z * a2.z + v.w * a2.w;
    }
#pragma unroll
    for (int o = 16; o; o >>= 1) {
        s1 += __shfl_xor_sync(0xffffffffu, s1, o);
        s2 += __shfl_xor_sync(0xffffffffu, s2, o);
    }
    if (lane == 0) {
        d_f1[row] = s1;
        d_f2[row] = s2;
        int b   = __float_as_int(s2);
        int key = b >= 0 ? b : (b ^ 0x7fffffff);
        atomicMax(&d_gmaxkey, key);
    }
}

// ---------------- factorized softmax weights ----------------
// e_ij = LReLU(f1_i + f2_j); with m_i = LReLU(f1_i + gm) >= rowmax(e),
// exp(e-m_i) = (s>0) ? A_i*B_j : C_i*D_j, all exponents <= 0 (safe).
__global__ void pexp_kernel() {
    int i = blockIdx.x * 256 + threadIdx.x;
    int kk = d_gmaxkey;
    float gm = __int_as_float(kk >= 0 ? kk : (kk ^ 0x7fffffff));
    float f1 = d_f1[i], f2 = d_f2[i];
    float u  = f1 + gm;
    float m  = u > 0.f ? u : LALPHA * u;
    d_A[i] = __expf(u - m);
    d_C[i] = __expf(LALPHA * u - m);
    float v = f2 - gm;
    d_B[i] = __expf(v);
    d_D[i] = __expf(LALPHA * v);
}

// ---------------- fused masked-softmax attention @ Wh ----------------
__global__ void __launch_bounds__(256, 2) attn_kernel(const int* __restrict__ adj) {
    __shared__ float WhS[32][256];                 // 32 KB
    __shared__ __align__(16) float Ps[32][66];     // [jj][row], pair-loadable
    __shared__ float f1s[64], As_s[64], Cs_s[64];

    int t    = threadIdx.x;
    int lane = t & 31, warp = t >> 5;
    int i0   = blockIdx.x * 64;
    int split = blockIdx.y;

    if (t < 64) {
        f1s[t]  = d_f1[i0 + t];
        As_s[t] = d_A[i0 + t];
        Cs_s[t] = d_C[i0 + t];
    }
    __syncthreads();

    ull acc2[8][4];
#pragma unroll
    for (int pr = 0; pr < 8; pr++)
#pragma unroll
        for (int c = 0; c < 4; c++) acc2[pr][c] = 0ull;
    float ssum[8];
#pragma unroll
    for (int q = 0; q < 8; q++) ssum[q] = 0.f;

    int c0 = (t & 63) * 4;        // 4 consecutive output cols
    int r0 = (t >> 6) * 16;       // 16 rows (8 pairs)

    int jbeg = split * (Nn / NSPLIT);
    int jend = jbeg + (Nn / NSPLIT);

    for (int j0 = jbeg; j0 < jend; j0 += 32) {
        // stage Wh[j0:j0+32, :]
#pragma unroll
        for (int q = 0; q < 8; q++) {
            int flat = q * 256 + t;
            int jj = flat >> 6, c4 = (flat & 63) * 4;
            *(float4*)&WhS[jj][c4] =
                *(const float4*)&d_Wh[(size_t)(j0 + jj) * FOUT + c4];
        }
        // P tile (no exp, no shuffles): warp w -> rows {q*8+w}, lane = jj
        float f2j = d_f2[j0 + lane];
        float Bj  = d_B[j0 + lane];
        float Dj  = d_D[j0 + lane];
#pragma unroll
        for (int q = 0; q < 8; q++) {
            int r  = q * 8 + warp;
            int ad = adj[(size_t)(i0 + r) * Nn + j0 + lane];
            float s = f1s[r] + f2j;
            float x = s > 0.f ? As_s[r] : Cs_s[r];
            float y = s > 0.f ? Bj : Dj;
            float p = (ad > 0) ? x * y : 0.f;
            Ps[lane][r] = p;
            ssum[q] += p;
        }
        __syncthreads();

        // packed f32x2 microkernel: acc[16 rows][4 cols] += P * Wh
#pragma unroll 2
        for (int jj = 0; jj < 32; jj++) {
            float4 wv = *(float4*)&WhS[jj][c0];
            ull wxx = dup2(wv.x), wyy = dup2(wv.y);
            ull wzz = dup2(wv.z), www = dup2(wv.w);
            const ull* pp = (const ull*)&Ps[jj][r0];
#pragma unroll
            for (int pr = 0; pr < 8; pr++) {
                ull p2 = pp[pr];
                ffma2(acc2[pr][0], p2, wxx);
                ffma2(acc2[pr][1], p2, wyy);
                ffma2(acc2[pr][2], p2, wzz);
                ffma2(acc2[pr][3], p2, www);
            }
        }
        __syncthreads();
    }

    // store partials: unpack row pairs
    float* ap = &d_accpart[((size_t)split * Nn + i0) * FOUT];
#pragma unroll
    for (int pr = 0; pr < 8; pr++) {
        float lo0, hi0, lo1, hi1, lo2, hi2, lo3, hi3;
        unpk(lo0, hi0, acc2[pr][0]);
        unpk(lo1, hi1, acc2[pr][1]);
        unpk(lo2, hi2, acc2[pr][2]);
        unpk(lo3, hi3, acc2[pr][3]);
        *(float4*)&ap[(size_t)(r0 + 2 * pr) * FOUT + c0] =
            make_float4(lo0, lo1, lo2, lo3);
        *(float4*)&ap[(size_t)(r0 + 2 * pr + 1) * FOUT + c0] =
            make_float4(hi0, hi1, hi2, hi3);
    }
    // one-time lane reduction of row sums
#pragma unroll
    for (int q = 0; q < 8; q++) {
        float s = ssum[q];
#pragma unroll
        for (int o = 16; o; o >>= 1) s += __shfl_xor_sync(0xffffffffu, s, o);
        if (lane == 0)
            d_spart[(size_t)split * Nn + i0 + q * 8 + warp] = s;
    }
}

// ---------------- combine splits, normalize, ELU ----------------
__global__ void combine_kernel(float* __restrict__ out) {
    int i = blockIdx.x, c = threadIdx.x;
    float s = d_spart[i] + d_spart[Nn + i];
    float v = d_accpart[(size_t)i * FOUT + c] +
              d_accpart[(size_t)Nn * FOUT + (size_t)i * FOUT + c];
    float x = v / s;
    out[(size_t)i * FOUT + c] = x > 0.f ? x : expm1f(x);
}

extern "C" void kernel_launch(void* const* d_in, const int* in_sizes, int n_in,
                              void* d_out, int out_size) {
    const float* h   = (const float*)d_in[0];
    const int*   adj = (const int*)d_in[1];
    const float* W   = (const float*)d_in[2];
    const float* a   = (const float*)d_in[3];
    float* out = (float*)d_out;

    init_kernel<<<1, 1>>>();
    dim3 g1(Nn / 64, FOUT / 64);
    gemm_wh<<<g1, 256>>>(h, W);
    f12_kernel<<<Nn / 8, 256>>>(a);
    pexp_kernel<<<Nn / 256, 256>>>();
    dim3 g3(Nn / 64, NSPLIT);
    attn_kernel<<<g3, 256>>>(adj);
    combine_kernel<<<Nn, 256>>>(out);
}

// round 5
// speedup vs baseline: 2.6040x; 2.0761x over previous
#include <cuda_runtime.h>
#include <cuda_bf16.h>
#include <cstdint>

#define Nn     8192
#define FIN    512
#define FOUT   256
#define LALPHA 0.2f
#define NSPLIT 2
#define M_TILE 128
#define KC     64
#define JHALF  (Nn / NSPLIT)      // 4096
#define NCHUNK (JHALF / KC)       // 64

// smem strides (in floats/words)
#define WS_STRIDE 264             // 256 data + 8 pad: b-frag banks (8m+q) conflict-free
#define PS_STRIDE 68              // a-frag banks (4q+m) conflict-free

// ---------------- scratch (device globals: allowed) ----------------
__device__ float d_Wh[(size_t)Nn * FOUT];            // 8 MB fp32
__device__ float d_Whr[(size_t)Nn * FOUT];           // 8 MB tf32-rounded
__device__ float d_f1[Nn];
__device__ float d_f2[Nn];
__device__ float d_A[Nn];   // exp(f1+gm-m)
__device__ float d_C[Nn];   // exp(0.2(f1+gm)-m)
__device__ float d_B[Nn];   // exp(f2-gm)
__device__ float d_D[Nn];   // exp(0.2(f2-gm))
__device__ int   d_gmaxkey;
__device__ float d_accpart[(size_t)NSPLIT * Nn * FOUT];  // 16 MB
__device__ float d_spart[(size_t)NSPLIT * Nn];

__device__ __forceinline__ uint32_t tf32_bits(float x) {
    uint32_t r; asm("cvt.rna.tf32.f32 %0, %1;" : "=r"(r) : "f"(x)); return r;
}
__device__ __forceinline__ void mma_tf32(float* d, uint32_t a0, uint32_t a1,
                                         uint32_t a2, uint32_t a3,
                                         uint32_t b0, uint32_t b1) {
    asm volatile(
        "mma.sync.aligned.m16n8k8.row.col.f32.tf32.tf32.f32 "
        "{%0,%1,%2,%3}, {%4,%5,%6,%7}, {%8,%9}, {%0,%1,%2,%3};"
        : "+f"(d[0]), "+f"(d[1]), "+f"(d[2]), "+f"(d[3])
        : "r"(a0), "r"(a1), "r"(a2), "r"(a3), "r"(b0), "r"(b1));
}

// ---------------- Wh = h @ W ----------------
__global__ void gemm_wh(const float* __restrict__ h, const float* __restrict__ W) {
    if (blockIdx.x == 0 && blockIdx.y == 0 && threadIdx.x == 0)
        d_gmaxkey = (int)0x80000000;
    __shared__ float As[16][64];
    __shared__ float Bs[16][64];
    int t  = threadIdx.x;
    int bm = blockIdx.x * 64, bn = blockIdx.y * 64;
    int r0 = (t >> 4) * 4, c0 = (t & 15) * 4;
    int arow = t >> 2, akq = (t & 3) * 4;
    int bkk = t >> 4, bn4 = (t & 15) * 4;

    float acc[4][4];
#pragma unroll
    for (int i = 0; i < 4; i++)
#pragma unroll
        for (int j = 0; j < 4; j++) acc[i][j] = 0.f;

    for (int k0 = 0; k0 < FIN; k0 += 16) {
        float4 av = *(const float4*)&h[(size_t)(bm + arow) * FIN + k0 + akq];
        As[akq + 0][arow] = av.x; As[akq + 1][arow] = av.y;
        As[akq + 2][arow] = av.z; As[akq + 3][arow] = av.w;
        *(float4*)&Bs[bkk][bn4] = *(const float4*)&W[(size_t)(k0 + bkk) * FOUT + bn + bn4];
        __syncthreads();
#pragma unroll
        for (int kk = 0; kk < 16; kk++) {
            float4 a4 = *(float4*)&As[kk][r0];
            float4 b4 = *(float4*)&Bs[kk][c0];
            acc[0][0] += a4.x * b4.x; acc[0][1] += a4.x * b4.y;
            acc[0][2] += a4.x * b4.z; acc[0][3] += a4.x * b4.w;
            acc[1][0] += a4.y * b4.x; acc[1][1] += a4.y * b4.y;
            acc[1][2] += a4.y * b4.z; acc[1][3] += a4.y * b4.w;
            acc[2][0] += a4.z * b4.x; acc[2][1] += a4.z * b4.y;
            acc[2][2] += a4.z * b4.z; acc[2][3] += a4.z * b4.w;
            acc[3][0] += a4.w * b4.x; acc[3][1] += a4.w * b4.y;
            acc[3][2] += a4.w * b4.z; acc[3][3] += a4.w * b4.w;
        }
        __syncthreads();
    }
#pragma unroll
    for (int i = 0; i < 4; i++)
        *(float4*)&d_Wh[(size_t)(bm + r0 + i) * FOUT + bn + c0] =
            make_float4(acc[i][0], acc[i][1], acc[i][2], acc[i][3]);
}

// ---------------- tf32-round Wh ----------------
__global__ void round_wh() {
    int i = (blockIdx.x * 256 + threadIdx.x) * 4;
    float4 v = *(const float4*)&d_Wh[i];
    float4 o;
    o.x = __uint_as_float(tf32_bits(v.x));
    o.y = __uint_as_float(tf32_bits(v.y));
    o.z = __uint_as_float(tf32_bits(v.z));
    o.w = __uint_as_float(tf32_bits(v.w));
    *(float4*)&d_Whr[i] = o;
}

// ---------------- f1, f2 and global max(f2) ----------------
__global__ void f12_kernel(const float* __restrict__ a) {
    int lane = threadIdx.x & 31, warp = threadIdx.x >> 5;
    int row  = blockIdx.x * 8 + warp;
    const float* wr = &d_Wh[(size_t)row * FOUT];
    float s1 = 0.f, s2 = 0.f;
#pragma unroll
    for (int q = 0; q < 2; q++) {
        int c = q * 128 + lane * 4;
        float4 v  = *(const float4*)&wr[c];
        float4 a1 = *(const float4*)&a[c];
        float4 a2 = *(const float4*)&a[FOUT + c];
        s1 += v.x * a1.x + v.y * a1.y + v.z * a1.z + v.w * a1.w;
        s2 += v.x * a2.x + v.y * a2.y + v.z * a2.z + v.w * a2.w;
    }
#pragma unroll
    for (int o = 16; o; o >>= 1) {
        s1 += __shfl_xor_sync(0xffffffffu, s1, o);
        s2 += __shfl_xor_sync(0xffffffffu, s2, o);
    }
    if (lane == 0) {
        d_f1[row] = s1;
        d_f2[row] = s2;
        int b   = __float_as_int(s2);
        int key = b >= 0 ? b : (b ^ 0x7fffffff);
        atomicMax(&d_gmaxkey, key);
    }
}

// ---------------- factorized softmax weights ----------------
// e=LReLU(f1_i+f2_j); m_i=LReLU(f1_i+gm)>=rowmax; exp(e-m)= s>0 ? A_i*B_j : C_i*D_j
__global__ void pexp_kernel() {
    int i = blockIdx.x * 256 + threadIdx.x;
    int kk = d_gmaxkey;
    float gm = __int_as_float(kk >= 0 ? kk : (kk ^ 0x7fffffff));
    float f1 = d_f1[i], f2 = d_f2[i];
    float u  = f1 + gm;
    float m  = u > 0.f ? u : LALPHA * u;
    d_A[i] = __expf(u - m);
    d_C[i] = __expf(LALPHA * u - m);
    float v = f2 - gm;
    d_B[i] = __expf(v);
    d_D[i] = __expf(LALPHA * v);
}

// ---------------- fused attention @ Wh via mma.sync tf32 ----------------
// 512 threads = 16 warps: 8 m-strips x 2 n-halves. Warp tile 16x128.
// Per 64-j chunk: stage Whr (64x256) + P tile (128x64) in smem, then
// 8 k-steps x 16 n-tiles of m16n8k8.
#define SMEM_DYN (KC * WS_STRIDE * 4 + M_TILE * PS_STRIDE * 4)   // 67584+34816

__global__ void __launch_bounds__(512, 1) attn_mma(const int* __restrict__ adj) {
    extern __shared__ char sm[];
    float*    WhS = (float*)sm;                            // [64][264]
    uint32_t* Ps  = (uint32_t*)(sm + KC * WS_STRIDE * 4);  // [128][68] tf32 bits

    int t    = threadIdx.x;
    int lane = t & 31, wid = t >> 5;
    int mstrip = wid >> 1, nhalf = wid & 1;
    int i0    = blockIdx.x * M_TILE;
    int split = blockIdx.y;
    int jbeg  = split * JHALF;

    // P-phase assignment: one row per thread, 16 cols
    int prow = t >> 2;                 // 0..127
    int pc0  = (t & 3) << 4;           // 0,16,32,48
    float f1r = d_f1[i0 + prow];
    float Ar  = d_A[i0 + prow];
    float Cr  = d_C[i0 + prow];
    float ssum = 0.f;
    const int4* adjrow = (const int4*)(adj + (size_t)(i0 + prow) * Nn);

    float acc[16][4];
#pragma unroll
    for (int n = 0; n < 16; n++)
#pragma unroll
        for (int u = 0; u < 4; u++) acc[n][u] = 0.f;

    int gID = lane >> 2, tID = lane & 3;
    int arow0 = mstrip * 16 + gID;

    for (int c = 0; c < NCHUNK; c++) {
        int jg = jbeg + c * KC;

        // ---- stage Whr chunk [64][256] ----
#pragma unroll
        for (int u = 0; u < 8; u++) {
            int f = u * 512 + t;
            int row = f >> 6, c4 = (f & 63) << 2;
            float4 v = *(const float4*)&d_Whr[(size_t)(jg + row) * FOUT + c4];
            *(float4*)&WhS[row * WS_STRIDE + c4] = v;
        }

        // ---- P tile [128][64] ----
#pragma unroll
        for (int u = 0; u < 4; u++) {
            int cc = pc0 + u * 4;
            int4   ad  = adjrow[(jg + cc) >> 2];
            float4 f2v = *(const float4*)&d_f2[jg + cc];
            float4 Bv  = *(const float4*)&d_B[jg + cc];
            float4 Dv  = *(const float4*)&d_D[jg + cc];
            float s0 = f1r + f2v.x, s1 = f1r + f2v.y;
            float s2 = f1r + f2v.z, s3 = f1r + f2v.w;
            float p0 = (ad.x > 0) ? (s0 > 0.f ? Ar * Bv.x : Cr * Dv.x) : 0.f;
            float p1 = (ad.y > 0) ? (s1 > 0.f ? Ar * Bv.y : Cr * Dv.y) : 0.f;
            float p2 = (ad.z > 0) ? (s2 > 0.f ? Ar * Bv.z : Cr * Dv.z) : 0.f;
            float p3 = (ad.w > 0) ? (s3 > 0.f ? Ar * Bv.w : Cr * Dv.w) : 0.f;
            ssum += (p0 + p1) + (p2 + p3);
            uint4 q = make_uint4(tf32_bits(p0), tf32_bits(p1),
                                 tf32_bits(p2), tf32_bits(p3));
            *(uint4*)&Ps[prow * PS_STRIDE + cc] = q;
        }
        __syncthreads();

        // ---- mma: 8 k-steps x 16 n-tiles ----
#pragma unroll
        for (int k = 0; k < 8; k++) {
            int kc = tID + 8 * k;
            uint32_t a0 = Ps[(arow0)     * PS_STRIDE + kc];
            uint32_t a1 = Ps[(arow0 + 8) * PS_STRIDE + kc];
            uint32_t a2 = Ps[(arow0)     * PS_STRIDE + kc + 4];
            uint32_t a3 = Ps[(arow0 + 8) * PS_STRIDE + kc + 4];
            int krow = k * 8 + tID;
#pragma unroll
            for (int n = 0; n < 16; n++) {
                int n0 = nhalf * 128 + n * 8 + gID;
                uint32_t b0 = __float_as_uint(WhS[krow * WS_STRIDE + n0]);
                uint32_t b1 = __float_as_uint(WhS[(krow + 4) * WS_STRIDE + n0]);
                mma_tf32(acc[n], a0, a1, a2, a3, b0, b1);
            }
        }
        __syncthreads();
    }

    // ---- row sums (4 threads share a row) ----
    ssum += __shfl_xor_sync(0xffffffffu, ssum, 1);
    ssum += __shfl_xor_sync(0xffffffffu, ssum, 2);
    if ((t & 3) == 0)
        d_spart[(size_t)split * Nn + i0 + prow] = ssum;

    // ---- store accumulators ----
    float* ap = &d_accpart[((size_t)split * Nn + i0) * FOUT];
    int r0 = mstrip * 16 + gID;
    int cb = nhalf * 128 + tID * 2;
#pragma unroll
    for (int n = 0; n < 16; n++) {
        *(float2*)&ap[(size_t)r0 * FOUT + cb + n * 8] =
            make_float2(acc[n][0], acc[n][1]);
        *(float2*)&ap[(size_t)(r0 + 8) * FOUT + cb + n * 8] =
            make_float2(acc[n][2], acc[n][3]);
    }
}

// ---------------- combine splits, normalize, ELU ----------------
__global__ void combine_kernel(float* __restrict__ out) {
    int i = blockIdx.x, c = threadIdx.x;
    float s = d_spart[i] + d_spart[Nn + i];
    float v = d_accpart[(size_t)i * FOUT + c] +
              d_accpart[(size_t)Nn * FOUT + (size_t)i * FOUT + c];
    float x = v / s;
    out[(size_t)i * FOUT + c] = x > 0.f ? x : expm1f(x);
}

extern "C" void kernel_launch(void* const* d_in, const int* in_sizes, int n_in,
                              void* d_out, int out_size) {
    const float* h   = (const float*)d_in[0];
    const int*   adj = (const int*)d_in[1];
    const float* W   = (const float*)d_in[2];
    const float* a   = (const float*)d_in[3];
    float* out = (float*)d_out;

    cudaFuncSetAttribute(attn_mma, cudaFuncAttributeMaxDynamicSharedMemorySize, SMEM_DYN);

    dim3 g1(Nn / 64, FOUT / 64);
    gemm_wh<<<g1, 256>>>(h, W);
    round_wh<<<(Nn * FOUT) / 1024, 256>>>();
    f12_kernel<<<Nn / 8, 256>>>(a);
    pexp_kernel<<<Nn / 256, 256>>>();
    dim3 g3(Nn / M_TILE, NSPLIT);
    attn_mma<<<g3, 512, SMEM_DYN>>>(adj);
    combine_kernel<<<Nn, 256>>>(out);
}